// round 16
// baseline (speedup 1.0000x reference)
#include <cuda_runtime.h>
#include <cuda_fp16.h>
#include <cstdint>

// Problem constants
#define B_ 4
#define T_ 1024
#define C_ 1024
#define H_ 16
#define D_ 64
#define WMAX 80           // logits j >= 80 are exactly zero
#define MTOT (B_ * T_)    // 4096
#define STAGE_BYTES 49152 // A 16KB + B 32KB per stage
#define NSTAGE 4
#define GEMM_SMEM (NSTAGE * STAGE_BYTES)   // 196608
#define NTAILP 8          // tail-sum partials per (b,h)

// Scratch (allocation-free rule: __device__ globals)
static __device__ float g_Sp[B_ * H_ * NTAILP * D_];
static __device__ __align__(16) __half g_qph[MTOT * 1024]; // 8 MB (Q proj, fp16)
static __device__ __align__(16) __half g_kph[MTOT * 1024]; // 8 MB (K proj, fp16)
static __device__ __align__(16) __half g_vph[MTOT * 1024]; // 8 MB (V proj, fp16)
static __device__ __align__(16) __half g_aq[MTOT * 1024];  // 8 MB
static __device__ __align__(16) __half g_ak[MTOT * 1024];  // 8 MB
static __device__ __align__(16) __half g_av[MTOT * 1024];  // 8 MB
static __device__ __align__(16) __half g_ap[MTOT * 1024];  // 8 MB
static __device__ __align__(16) __half g_wq[C_ * 1024];    // 2 MB
static __device__ __align__(16) __half g_wk[C_ * 1024];    // 2 MB
static __device__ __align__(16) __half g_wv[C_ * 1024];    // 2 MB
static __device__ __align__(16) __half g_wp[C_ * 1024];    // 2 MB

// ---------------------------------------------------------------------------
// PTX helpers (plain sm_103-safe)
// ---------------------------------------------------------------------------
__device__ __forceinline__ uint32_t smem_u32(const void* p) {
    uint32_t a;
    asm("{ .reg .u64 t; cvta.to.shared.u64 t, %1; cvt.u32.u64 %0, t; }" : "=r"(a) : "l"(p));
    return a;
}
__device__ __forceinline__ void cp16(uint32_t dst, const void* src) {
    asm volatile("cp.async.cg.shared.global [%0], [%1], 16;" :: "r"(dst), "l"(src));
}
#define CP_COMMIT() asm volatile("cp.async.commit_group;" ::: "memory")
#define CP_WAIT(n)  asm volatile("cp.async.wait_group %0;" :: "n"(n) : "memory")

#define LDSM4(r0, r1, r2, r3, addr) \
    asm volatile("ldmatrix.sync.aligned.m8n8.x4.shared.b16 {%0,%1,%2,%3}, [%4];" \
                 : "=r"(r0), "=r"(r1), "=r"(r2), "=r"(r3) : "r"(addr))

#define MMA_F16(d, a, b0, b1) \
    asm volatile("mma.sync.aligned.m16n8k16.row.col.f32.f16.f16.f32 " \
                 "{%0,%1,%2,%3},{%4,%5,%6,%7},{%8,%9},{%0,%1,%2,%3};" \
                 : "+f"((d)[0]), "+f"((d)[1]), "+f"((d)[2]), "+f"((d)[3]) \
                 : "r"((a)[0]), "r"((a)[1]), "r"((a)[2]), "r"((a)[3]), \
                   "r"(b0), "r"(b1))

__device__ __forceinline__ uint32_t swz(uint32_t off) {   // SW128
    return off ^ ((off >> 3) & 0x70);
}

// ---------------------------------------------------------------------------
// Unified split: 7 conversion jobs in one launch (blockIdx.y = job).
// All jobs are 1-term fp16 (pitch 1024).
// ---------------------------------------------------------------------------
struct SplitJobs {
    const float* src[7];
    __half*      dst[7];
    int          n4[7];
};

__global__ __launch_bounds__(256) void split_all_kernel(SplitJobs J)
{
    const int j = blockIdx.y;
    int i = blockIdx.x * 256 + threadIdx.x;
    if (i >= J.n4[j]) return;
    float4 v = ((const float4*)J.src[j])[i];
    __half h0 = __float2half_rn(v.x);
    __half h1 = __float2half_rn(v.y);
    __half h2 = __float2half_rn(v.z);
    __half h3 = __float2half_rn(v.w);
    uint2 ph;
    ph.x = ((uint32_t)__half_as_ushort(h1) << 16) | __half_as_ushort(h0);
    ph.y = ((uint32_t)__half_as_ushort(h3) << 16) | __half_as_ushort(h2);
    ((uint2*)J.dst[j])[i] = ph;
}

// ---------------------------------------------------------------------------
// fp16 NT GEMM via mma.sync m16n8k16: C[m,n] = sum_k A[m,k]*W[n,k] (+bias)
// M=4096, N=1024, K=1024 (KT=16). CTA 128x256, 8 warps (2x4), warp tile
// 64x64. SW128 smem, 4-stage cp.async pipeline. blockIdx.z selects the job.
// Per-job output: fp32 (Cf) or fp16 (Ch, pitch 1024).
// ---------------------------------------------------------------------------
struct GemmJobs {
    const __half* A[3];
    const __half* W[3];
    const float*  bias[3];
    float*        Cf[3];   // fp32 output (or nullptr)
    __half*       Ch[3];   // fp16 output (or nullptr)
};

__global__ __launch_bounds__(256, 1) void gemm_f16s(GemmJobs Js)
{
    extern __shared__ char smem[];
    const int z = blockIdx.z;
    const __half* __restrict__ A3 = Js.A[z];
    const __half* __restrict__ W3 = Js.W[z];
    const int KT = 16;
    const uint32_t sb = smem_u32(smem);
    const int tid  = threadIdx.x;
    const int lane = tid & 31;
    const int wid  = tid >> 5;
    const int bm   = blockIdx.y * 128;
    const int bn   = blockIdx.x * 256;
    const int wm   = (wid >> 2) * 64;
    const int wn   = (wid & 3) * 64;

    float acc[4][8][4];
#pragma unroll
    for (int i = 0; i < 4; i++)
#pragma unroll
        for (int j = 0; j < 8; j++)
#pragma unroll
            for (int c = 0; c < 4; c++) acc[i][j][c] = 0.f;

    auto issue = [&](int kt) {
        const int stage = kt & (NSTAGE - 1);
        const int k0 = kt * 64;
#pragma unroll
        for (int it = 0; it < 12; it++) {
            int idx = tid + it * 256;          // 0..3071
            int isB = idx >= 1024;
            int l   = isB ? (idx - 1024) : idx;
            int row = l >> 3, ch = l & 7;
            const __half* src = isB
                ? W3 + (size_t)(bn + row) * 1024 + k0 + ch * 8
                : A3 + (size_t)(bm + row) * 1024 + k0 + ch * 8;
            uint32_t off = (uint32_t)row * 128 + ch * 16;
            uint32_t dst = sb + stage * STAGE_BYTES + (isB ? 16384 : 0) + swz(off);
            cp16(dst, src);
        }
    };

    issue(0); CP_COMMIT();
    issue(1); CP_COMMIT();
    issue(2); CP_COMMIT();

    const uint32_t rA = wm + (lane & 7) + ((lane >> 3) & 1) * 8;
    const uint32_t kA = ((lane >> 4) & 1) * 16;
    const uint32_t rB = wn + (lane & 7) + ((lane >> 4) & 1) * 8;
    const uint32_t kB = ((lane >> 3) & 1) * 16;

#pragma unroll 1
    for (int kt = 0; kt < KT; kt++) {
        CP_WAIT(2);
        __syncthreads();
        if (kt + 3 < KT) issue(kt + 3);
        CP_COMMIT();

        const uint32_t sA = sb + (kt & (NSTAGE - 1)) * STAGE_BYTES;
        const uint32_t sB = sA + 16384;
#pragma unroll
        for (int ks = 0; ks < 4; ks++) {
            uint32_t a[4][4], b[4][4];
#pragma unroll
            for (int ti = 0; ti < 4; ti++) {
                uint32_t off = (rA + ti * 16) * 128 + ks * 32 + kA;
                LDSM4(a[ti][0], a[ti][1], a[ti][2], a[ti][3], sA + swz(off));
            }
#pragma unroll
            for (int tp = 0; tp < 4; tp++) {
                uint32_t off = (rB + tp * 16) * 128 + ks * 32 + kB;
                LDSM4(b[tp][0], b[tp][1], b[tp][2], b[tp][3], sB + swz(off));
            }
#pragma unroll
            for (int ti = 0; ti < 4; ti++)
#pragma unroll
                for (int tj = 0; tj < 8; tj++)
                    MMA_F16(acc[ti][tj], a[ti], b[tj >> 1][(tj & 1) * 2],
                            b[tj >> 1][(tj & 1) * 2 + 1]);
        }
    }

    // Epilogue
    const float* bias = Js.bias[z];
    const int col0 = bn + wn + (lane & 3) * 2;
    const int r0   = lane >> 2;
    if (Js.Ch[z]) {
        __half* __restrict__ Ch = Js.Ch[z];
#pragma unroll
        for (int ti = 0; ti < 4; ti++) {
            const int row = bm + wm + ti * 16 + r0;
#pragma unroll
            for (int tj = 0; tj < 8; tj++) {
                *(__half2*)(Ch + (size_t)row * 1024 + col0 + tj * 8) =
                    __floats2half2_rn(acc[ti][tj][0], acc[ti][tj][1]);
                *(__half2*)(Ch + (size_t)(row + 8) * 1024 + col0 + tj * 8) =
                    __floats2half2_rn(acc[ti][tj][2], acc[ti][tj][3]);
            }
        }
    } else {
        float* __restrict__ Cout = Js.Cf[z];
#pragma unroll
        for (int ti = 0; ti < 4; ti++) {
            const int row = bm + wm + ti * 16 + r0;
#pragma unroll
            for (int tj = 0; tj < 8; tj++) {
                float2 bv = bias ? *(const float2*)(bias + col0 + tj * 8)
                                 : make_float2(0.f, 0.f);
                float2 v0 = make_float2(acc[ti][tj][0] + bv.x, acc[ti][tj][1] + bv.y);
                float2 v1 = make_float2(acc[ti][tj][2] + bv.x, acc[ti][tj][3] + bv.y);
                *(float2*)(Cout + (size_t)row * C_ + col0 + tj * 8)       = v0;
                *(float2*)(Cout + (size_t)(row + 8) * C_ + col0 + tj * 8) = v1;
            }
        }
    }
}

// ---------------------------------------------------------------------------
// Tail V partial sums (fp16 V): 512 blocks (64 bh x 8 parts), each sums
// 118 rows via half2 loads. Sp stays fp32.
// ---------------------------------------------------------------------------
__global__ __launch_bounds__(256) void sum_tail_kernel(
    const __half* __restrict__ vph, float* __restrict__ Sp)
{
    __shared__ float2 part[8][32];
    const int bh   = blockIdx.x;         // 0..63
    const int prt  = blockIdx.y;         // 0..7
    const int b    = bh >> 4, h = bh & 15;
    const int tid  = threadIdx.x;
    const int c2 = tid & 31;             // half2 column
    const int p  = tid >> 5;             // 0..7
    const int j0 = WMAX + prt * 118;     // 944 = 8*118
    const size_t base = (size_t)b * T_ * 1024 + (size_t)h * D_ + c2 * 2;
    float2 s = make_float2(0.f, 0.f);
    for (int r = p; r < 118; r += 8) {
        float2 t = __half22float2(*(const __half2*)(vph + base + (size_t)(j0 + r) * 1024));
        s.x += t.x; s.y += t.y;
    }
    part[p][c2] = s;
    __syncthreads();
    if (tid < 32) {
        float2 acc = make_float2(0.f, 0.f);
#pragma unroll
        for (int pp = 0; pp < 8; pp++) {
            acc.x += part[pp][tid].x;
            acc.y += part[pp][tid].y;
        }
        float* dst = Sp + (bh * NTAILP + prt) * D_ + tid * 2;
        dst[0] = acc.x;
        dst[1] = acc.y;
    }
}

// ---------------------------------------------------------------------------
// Attention: 172.8us configuration with ONE change: the softmax max pass is
// removed. Logits are windowed sums with std~0.7 (max over dataset ~<6), so
// unnormalized softmax a_j = e^{w_j} / (sum e^{w} + 944) is fp32-safe.
// This cuts a 5-step shuffle-reduce chain + one exp from the serial path.
// Epilogue writes 1-term fp16 Oh into the P GEMM A-buffer (pitch 1024).
// ---------------------------------------------------------------------------
__global__ __launch_bounds__(256) void attn_kernel(
    const __half* __restrict__ qph, const __half* __restrict__ kph,
    const __half* __restrict__ vph, const float* __restrict__ gSp,
    __half* __restrict__ o1)
{
    __shared__ float Vs[WMAX][D_];                     // 20 KB
    __shared__ __align__(16) float wbuf[8][4][WMAX];   // 10 KB
    __shared__ float scs[8][4][68];                    // 8.5 KB

    const int tid   = threadIdx.x;
    const int lane  = tid & 31;
    const int w     = tid >> 5;
    const int chunk = blockIdx.x;        // 0..7
    const int h     = blockIdx.y;
    const int b     = blockIdx.z;
    const size_t hbase = (size_t)b * T_ * 1024 + (size_t)h * D_;

    for (int idx = tid; idx < WMAX * 32; idx += 256) {
        int j = idx >> 5, c2 = idx & 31;
        float2 t = __half22float2(
            *(const __half2*)(vph + hbase + (size_t)j * 1024 + c2 * 2));
        Vs[j][c2 * 2]     = t.x;
        Vs[j][c2 * 2 + 1] = t.y;
    }
    __syncthreads();

    // S = sum of 8 tail partials
    float2 S2 = make_float2(0.f, 0.f);
    {
        const float* pp = gSp + (b * H_ + h) * NTAILP * D_ + lane * 2;
#pragma unroll
        for (int p = 0; p < NTAILP; p++) {
            float2 t = *(const float2*)(pp + p * D_);
            S2.x += t.x; S2.y += t.y;
        }
    }

    for (int rq = 0; rq < 4; rq++) {
        const int ibase = chunk * 128 + w * 16 + rq * 4;
        float cr[4];
#pragma unroll
        for (int rr = 0; rr < 4; rr++) {
            const int i = ibase + rr;
            const float2 qv = __half22float2(
                *(const __half2*)(qph + hbase + (size_t)i * 1024 + lane * 2));
            const float2 kv = __half22float2(
                *(const __half2*)(kph + hbase + (size_t)i * 1024 + lane * 2));
            const float p0 = qv.x * kv.x * 0.125f;
            const float p1 = qv.y * kv.y * 0.125f;

            float s = p0 + p1;
#pragma unroll
            for (int off = 1; off < 32; off <<= 1) {
                float t = __shfl_up_sync(0xffffffffu, s, off);
                if (lane >= off) s += t;
            }
            scs[w][rr][2 * lane + 1] = s - p1;
            scs[w][rr][2 * lane + 2] = s;
            if (lane == 0) scs[w][rr][0] = 0.f;
            __syncwarp();

            // unnormalized: e_j = exp(w_j); tail logits contribute 944 * e^0
            float ev[3];
            float zs = 0.f;
#pragma unroll
            for (int t3 = 0; t3 < 3; t3++) {
                int j = lane + 32 * t3;
                if (j < WMAX) {
                    int st = (j > 16) ? (j - 16) : 0;
                    int en = (j + 16 < 64) ? (j + 16) : 64;
                    float e = __expf(scs[w][rr][en] - scs[w][rr][st]);
                    ev[t3] = e;
                    zs += e;
                }
            }
#pragma unroll
            for (int off = 16; off >= 1; off >>= 1)
                zs += __shfl_xor_sync(0xffffffffu, zs, off);

            const float invZ = 1.0f / (zs + 944.0f);
#pragma unroll
            for (int t3 = 0; t3 < 3; t3++) {
                int j = lane + 32 * t3;
                if (j < WMAX) wbuf[w][rr][j] = ev[t3] * invZ;
            }
            cr[rr] = invZ;
            __syncwarp();
        }

        float2 acc[4];
#pragma unroll
        for (int rr = 0; rr < 4; rr++)
            acc[rr] = make_float2(cr[rr] * S2.x, cr[rr] * S2.y);

#pragma unroll 1
        for (int j4 = 0; j4 < WMAX / 4; j4++) {
            const int j = j4 * 4;
            const float2 vv0 = *(const float2*)&Vs[j + 0][lane * 2];
            const float2 vv1 = *(const float2*)&Vs[j + 1][lane * 2];
            const float2 vv2 = *(const float2*)&Vs[j + 2][lane * 2];
            const float2 vv3 = *(const float2*)&Vs[j + 3][lane * 2];
#pragma unroll
            for (int rr = 0; rr < 4; rr++) {
                const float4 aw = *(const float4*)&wbuf[w][rr][j];
                acc[rr].x = fmaf(aw.x, vv0.x, acc[rr].x);
                acc[rr].y = fmaf(aw.x, vv0.y, acc[rr].y);
                acc[rr].x = fmaf(aw.y, vv1.x, acc[rr].x);
                acc[rr].y = fmaf(aw.y, vv1.y, acc[rr].y);
                acc[rr].x = fmaf(aw.z, vv2.x, acc[rr].x);
                acc[rr].y = fmaf(aw.z, vv2.y, acc[rr].y);
                acc[rr].x = fmaf(aw.w, vv3.x, acc[rr].x);
                acc[rr].y = fmaf(aw.w, vv3.y, acc[rr].y);
            }
        }

#pragma unroll
        for (int rr = 0; rr < 4; rr++) {
            const __half h0 = __float2half_rn(acc[rr].x);
            const __half h1 = __float2half_rn(acc[rr].y);
            const size_t rb = (size_t)(b * T_ + ibase + rr) * 1024 + h * D_ + lane * 2;
            *(__half2*)(o1 + rb) = __halves2half2(h0, h1);
        }
        __syncwarp();
    }
}

// ---------------------------------------------------------------------------
extern "C" void kernel_launch(void* const* d_in, const int* in_sizes, int n_in,
                              void* d_out, int out_size)
{
    const float* q  = (const float*)d_in[0];
    const float* k  = (const float*)d_in[1];
    const float* v  = (const float*)d_in[2];
    const float* Wq = (const float*)d_in[3];
    const float* Wk = (const float*)d_in[4];
    const float* Wv = (const float*)d_in[5];
    const float* Wp = (const float*)d_in[6];
    const float* bp = (const float*)d_in[7];
    float* out = (float*)d_out;

    float *gSp;
    __half *qph, *kph, *vph, *aq, *ak, *av, *ap, *wq, *wk, *wv, *wp;
    cudaGetSymbolAddress((void**)&gSp, g_Sp);
    cudaGetSymbolAddress((void**)&qph, g_qph);
    cudaGetSymbolAddress((void**)&kph, g_kph);
    cudaGetSymbolAddress((void**)&vph, g_vph);
    cudaGetSymbolAddress((void**)&aq, g_aq);
    cudaGetSymbolAddress((void**)&ak, g_ak);
    cudaGetSymbolAddress((void**)&av, g_av);
    cudaGetSymbolAddress((void**)&ap, g_ap);
    cudaGetSymbolAddress((void**)&wq, g_wq);
    cudaGetSymbolAddress((void**)&wk, g_wk);
    cudaGetSymbolAddress((void**)&wv, g_wv);
    cudaGetSymbolAddress((void**)&wp, g_wp);

    cudaFuncSetAttribute(gemm_f16s, cudaFuncAttributeMaxDynamicSharedMemorySize, GEMM_SMEM);

    const int nA4 = MTOT * C_ / 4;   // 1,048,576
    const int nW4 = C_ * C_ / 4;     // 262,144

    // All 7 splits (all 1-term fp16) in one launch
    SplitJobs J;
    J.src[0] = q;  J.dst[0] = aq; J.n4[0] = nA4;
    J.src[1] = k;  J.dst[1] = ak; J.n4[1] = nA4;
    J.src[2] = v;  J.dst[2] = av; J.n4[2] = nA4;
    J.src[3] = Wq; J.dst[3] = wq; J.n4[3] = nW4;
    J.src[4] = Wk; J.dst[4] = wk; J.n4[4] = nW4;
    J.src[5] = Wv; J.dst[5] = wv; J.n4[5] = nW4;
    J.src[6] = Wp; J.dst[6] = wp; J.n4[6] = nW4;
    split_all_kernel<<<dim3(nA4 / 256, 7), 256>>>(J);

    // Fused Q/K/V projections: all outputs fp16 (qph/kph/vph)
    GemmJobs G;
    G.A[0] = av; G.W[0] = wv; G.bias[0] = nullptr; G.Cf[0] = nullptr; G.Ch[0] = vph;
    G.A[1] = aq; G.W[1] = wq; G.bias[1] = nullptr; G.Cf[1] = nullptr; G.Ch[1] = qph;
    G.A[2] = ak; G.W[2] = wk; G.bias[2] = nullptr; G.Cf[2] = nullptr; G.Ch[2] = kph;
    gemm_f16s<<<dim3(C_ / 256, MTOT / 128, 3), 256, GEMM_SMEM>>>(G);

    sum_tail_kernel<<<dim3(B_ * H_, NTAILP), 256>>>(vph, gSp);

    dim3 ga(T_ / 128, H_, B_);           // 512 CTAs
    attn_kernel<<<ga, 256>>>(qph, kph, vph, gSp, ap);

    // Output projection (+bias), 1-term, fp32 out
    GemmJobs P;
    P.A[0] = ap; P.W[0] = wp; P.bias[0] = bp; P.Cf[0] = out; P.Ch[0] = nullptr;
    P.A[1] = ap; P.W[1] = wp; P.bias[1] = bp; P.Cf[1] = out; P.Ch[1] = nullptr;
    P.A[2] = ap; P.W[2] = wp; P.bias[2] = bp; P.Cf[2] = out; P.Ch[2] = nullptr;
    gemm_f16s<<<dim3(C_ / 256, MTOT / 128, 1), 256, GEMM_SMEM>>>(P);
}

// round 17
// speedup vs baseline: 1.0526x; 1.0526x over previous
#include <cuda_runtime.h>
#include <cuda_fp16.h>
#include <cstdint>

// Problem constants
#define B_ 4
#define T_ 1024
#define C_ 1024
#define H_ 16
#define D_ 64
#define WMAX 80           // logits j >= 80 are exactly zero
#define MTOT (B_ * T_)    // 4096
#define STAGE_BYTES 49152 // A 16KB + B 32KB per stage
#define NSTAGE 4
#define GEMM_SMEM (NSTAGE * STAGE_BYTES)   // 196608

// Scratch (allocation-free rule: __device__ globals)
static __device__ float g_S[B_ * H_ * D_];                 // V column sums
static __device__ __align__(16) __half g_qph[MTOT * 1024]; // 8 MB (Q proj, fp16)
static __device__ __align__(16) __half g_kph[MTOT * 1024]; // 8 MB (K proj, fp16)
static __device__ __align__(16) __half g_vph[MTOT * 1024]; // 8 MB (V proj, fp16)
static __device__ __align__(16) __half g_aq[MTOT * 1024];  // 8 MB
static __device__ __align__(16) __half g_ak[MTOT * 1024];  // 8 MB
static __device__ __align__(16) __half g_av[MTOT * 1024];  // 8 MB
static __device__ __align__(16) __half g_ap[MTOT * 1024];  // 8 MB
static __device__ __align__(16) __half g_wq[C_ * 1024];    // 2 MB
static __device__ __align__(16) __half g_wk[C_ * 1024];    // 2 MB
static __device__ __align__(16) __half g_wv[C_ * 1024];    // 2 MB
static __device__ __align__(16) __half g_wp[C_ * 1024];    // 2 MB

// ---------------------------------------------------------------------------
// PTX helpers (plain sm_103-safe)
// ---------------------------------------------------------------------------
__device__ __forceinline__ uint32_t smem_u32(const void* p) {
    uint32_t a;
    asm("{ .reg .u64 t; cvta.to.shared.u64 t, %1; cvt.u32.u64 %0, t; }" : "=r"(a) : "l"(p));
    return a;
}
__device__ __forceinline__ void cp16(uint32_t dst, const void* src) {
    asm volatile("cp.async.cg.shared.global [%0], [%1], 16;" :: "r"(dst), "l"(src));
}
#define CP_COMMIT() asm volatile("cp.async.commit_group;" ::: "memory")
#define CP_WAIT(n)  asm volatile("cp.async.wait_group %0;" :: "n"(n) : "memory")

#define LDSM4(r0, r1, r2, r3, addr) \
    asm volatile("ldmatrix.sync.aligned.m8n8.x4.shared.b16 {%0,%1,%2,%3}, [%4];" \
                 : "=r"(r0), "=r"(r1), "=r"(r2), "=r"(r3) : "r"(addr))

#define MMA_F16(d, a, b0, b1) \
    asm volatile("mma.sync.aligned.m16n8k16.row.col.f32.f16.f16.f32 " \
                 "{%0,%1,%2,%3},{%4,%5,%6,%7},{%8,%9},{%0,%1,%2,%3};" \
                 : "+f"((d)[0]), "+f"((d)[1]), "+f"((d)[2]), "+f"((d)[3]) \
                 : "r"((a)[0]), "r"((a)[1]), "r"((a)[2]), "r"((a)[3]), \
                   "r"(b0), "r"(b1))

__device__ __forceinline__ uint32_t swz(uint32_t off) {   // SW128
    return off ^ ((off >> 3) & 0x70);
}

// ---------------------------------------------------------------------------
// Unified split: 7 conversion jobs in one launch (blockIdx.y = job).
// All jobs are 1-term fp16 (pitch 1024). Job 0 / block 0 also zeroes g_S
// (ordered before the V-GEMM's atomic column sums by stream order).
// ---------------------------------------------------------------------------
struct SplitJobs {
    const float* src[7];
    __half*      dst[7];
    int          n4[7];
    float*       S;
};

__global__ __launch_bounds__(256) void split_all_kernel(SplitJobs J)
{
    const int j = blockIdx.y;
    if (j == 0 && blockIdx.x == 0) {
        for (int t = threadIdx.x; t < B_ * H_ * D_; t += 256)
            J.S[t] = 0.f;
    }
    int i = blockIdx.x * 256 + threadIdx.x;
    if (i >= J.n4[j]) return;
    float4 v = ((const float4*)J.src[j])[i];
    __half h0 = __float2half_rn(v.x);
    __half h1 = __float2half_rn(v.y);
    __half h2 = __float2half_rn(v.z);
    __half h3 = __float2half_rn(v.w);
    uint2 ph;
    ph.x = ((uint32_t)__half_as_ushort(h1) << 16) | __half_as_ushort(h0);
    ph.y = ((uint32_t)__half_as_ushort(h3) << 16) | __half_as_ushort(h2);
    ((uint2*)J.dst[j])[i] = ph;
}

// ---------------------------------------------------------------------------
// fp16 NT GEMM via mma.sync m16n8k16: C[m,n] = sum_k A[m,k]*W[n,k] (+bias)
// M=4096, N=1024, K=1024 (KT=16). CTA 128x256, 8 warps (2x4), warp tile
// 64x64. SW128 smem, 4-stage cp.async pipeline. blockIdx.z selects the job.
// Per-job output: fp32 (Cf) or fp16 (Ch, pitch 1024). If Ssum[z] != null the
// epilogue also atomically accumulates per-batch column sums (V job).
// ---------------------------------------------------------------------------
struct GemmJobs {
    const __half* A[3];
    const __half* W[3];
    const float*  bias[3];
    float*        Cf[3];   // fp32 output (or nullptr)
    __half*       Ch[3];   // fp16 output (or nullptr)
    float*        Ssum[3]; // column-sum accumulator (or nullptr)
};

__global__ __launch_bounds__(256, 1) void gemm_f16s(GemmJobs Js)
{
    extern __shared__ char smem[];
    const int z = blockIdx.z;
    const __half* __restrict__ A3 = Js.A[z];
    const __half* __restrict__ W3 = Js.W[z];
    const int KT = 16;
    const uint32_t sb = smem_u32(smem);
    const int tid  = threadIdx.x;
    const int lane = tid & 31;
    const int wid  = tid >> 5;
    const int bm   = blockIdx.y * 128;
    const int bn   = blockIdx.x * 256;
    const int wm   = (wid >> 2) * 64;
    const int wn   = (wid & 3) * 64;

    float acc[4][8][4];
#pragma unroll
    for (int i = 0; i < 4; i++)
#pragma unroll
        for (int j = 0; j < 8; j++)
#pragma unroll
            for (int c = 0; c < 4; c++) acc[i][j][c] = 0.f;

    auto issue = [&](int kt) {
        const int stage = kt & (NSTAGE - 1);
        const int k0 = kt * 64;
#pragma unroll
        for (int it = 0; it < 12; it++) {
            int idx = tid + it * 256;          // 0..3071
            int isB = idx >= 1024;
            int l   = isB ? (idx - 1024) : idx;
            int row = l >> 3, ch = l & 7;
            const __half* src = isB
                ? W3 + (size_t)(bn + row) * 1024 + k0 + ch * 8
                : A3 + (size_t)(bm + row) * 1024 + k0 + ch * 8;
            uint32_t off = (uint32_t)row * 128 + ch * 16;
            uint32_t dst = sb + stage * STAGE_BYTES + (isB ? 16384 : 0) + swz(off);
            cp16(dst, src);
        }
    };

    issue(0); CP_COMMIT();
    issue(1); CP_COMMIT();
    issue(2); CP_COMMIT();

    const uint32_t rA = wm + (lane & 7) + ((lane >> 3) & 1) * 8;
    const uint32_t kA = ((lane >> 4) & 1) * 16;
    const uint32_t rB = wn + (lane & 7) + ((lane >> 4) & 1) * 8;
    const uint32_t kB = ((lane >> 3) & 1) * 16;

#pragma unroll 1
    for (int kt = 0; kt < KT; kt++) {
        CP_WAIT(2);
        __syncthreads();
        if (kt + 3 < KT) issue(kt + 3);
        CP_COMMIT();

        const uint32_t sA = sb + (kt & (NSTAGE - 1)) * STAGE_BYTES;
        const uint32_t sB = sA + 16384;
#pragma unroll
        for (int ks = 0; ks < 4; ks++) {
            uint32_t a[4][4], b[4][4];
#pragma unroll
            for (int ti = 0; ti < 4; ti++) {
                uint32_t off = (rA + ti * 16) * 128 + ks * 32 + kA;
                LDSM4(a[ti][0], a[ti][1], a[ti][2], a[ti][3], sA + swz(off));
            }
#pragma unroll
            for (int tp = 0; tp < 4; tp++) {
                uint32_t off = (rB + tp * 16) * 128 + ks * 32 + kB;
                LDSM4(b[tp][0], b[tp][1], b[tp][2], b[tp][3], sB + swz(off));
            }
#pragma unroll
            for (int ti = 0; ti < 4; ti++)
#pragma unroll
                for (int tj = 0; tj < 8; tj++)
                    MMA_F16(acc[ti][tj], a[ti], b[tj >> 1][(tj & 1) * 2],
                            b[tj >> 1][(tj & 1) * 2 + 1]);
        }
    }

    // Epilogue
    const float* bias = Js.bias[z];
    const int col0 = bn + wn + (lane & 3) * 2;
    const int r0   = lane >> 2;
    if (Js.Ch[z]) {
        __half* __restrict__ Ch = Js.Ch[z];
#pragma unroll
        for (int ti = 0; ti < 4; ti++) {
            const int row = bm + wm + ti * 16 + r0;
#pragma unroll
            for (int tj = 0; tj < 8; tj++) {
                *(__half2*)(Ch + (size_t)row * 1024 + col0 + tj * 8) =
                    __floats2half2_rn(acc[ti][tj][0], acc[ti][tj][1]);
                *(__half2*)(Ch + (size_t)(row + 8) * 1024 + col0 + tj * 8) =
                    __floats2half2_rn(acc[ti][tj][2], acc[ti][tj][3]);
            }
        }
        if (Js.Ssum[z]) {
            // per-batch column sums of this CTA's 128 rows (fp32 accs)
            float* S = Js.Ssum[z] + (size_t)(bm >> 10) * 1024;
#pragma unroll
            for (int tj = 0; tj < 8; tj++) {
                float px = 0.f, py = 0.f;
#pragma unroll
                for (int ti = 0; ti < 4; ti++) {
                    px += acc[ti][tj][0] + acc[ti][tj][2];
                    py += acc[ti][tj][1] + acc[ti][tj][3];
                }
                px += __shfl_xor_sync(0xffffffffu, px, 4);
                py += __shfl_xor_sync(0xffffffffu, py, 4);
                px += __shfl_xor_sync(0xffffffffu, px, 8);
                py += __shfl_xor_sync(0xffffffffu, py, 8);
                px += __shfl_xor_sync(0xffffffffu, px, 16);
                py += __shfl_xor_sync(0xffffffffu, py, 16);
                if ((lane >> 2) == 0) {
                    atomicAdd(S + col0 + tj * 8,     px);
                    atomicAdd(S + col0 + tj * 8 + 1, py);
                }
            }
        }
    } else {
        float* __restrict__ Cout = Js.Cf[z];
#pragma unroll
        for (int ti = 0; ti < 4; ti++) {
            const int row = bm + wm + ti * 16 + r0;
#pragma unroll
            for (int tj = 0; tj < 8; tj++) {
                float2 bv = bias ? *(const float2*)(bias + col0 + tj * 8)
                                 : make_float2(0.f, 0.f);
                float2 v0 = make_float2(acc[ti][tj][0] + bv.x, acc[ti][tj][1] + bv.y);
                float2 v1 = make_float2(acc[ti][tj][2] + bv.x, acc[ti][tj][3] + bv.y);
                *(float2*)(Cout + (size_t)row * C_ + col0 + tj * 8)       = v0;
                *(float2*)(Cout + (size_t)(row + 8) * C_ + col0 + tj * 8) = v1;
            }
        }
    }
}

// ---------------------------------------------------------------------------
// Attention: 172.8us configuration (512 CTAs, regs 48, no max pass).
// Tail-V sum now derived in-kernel: S_tail = S_total[b,h] - sum_{j<80} Vs[j],
// using the V-GEMM's atomic column sums (sum_tail kernel eliminated).
// Epilogue writes 1-term fp16 Oh into the P GEMM A-buffer (pitch 1024).
// ---------------------------------------------------------------------------
__global__ __launch_bounds__(256) void attn_kernel(
    const __half* __restrict__ qph, const __half* __restrict__ kph,
    const __half* __restrict__ vph, const float* __restrict__ gS,
    __half* __restrict__ o1)
{
    __shared__ float Vs[WMAX][D_];                     // 20 KB
    __shared__ __align__(16) float wbuf[8][4][WMAX];   // 10 KB
    __shared__ float scs[8][4][68];                    // 8.5 KB

    const int tid   = threadIdx.x;
    const int lane  = tid & 31;
    const int w     = tid >> 5;
    const int chunk = blockIdx.x;        // 0..7
    const int h     = blockIdx.y;
    const int b     = blockIdx.z;
    const size_t hbase = (size_t)b * T_ * 1024 + (size_t)h * D_;

    for (int idx = tid; idx < WMAX * 32; idx += 256) {
        int j = idx >> 5, c2 = idx & 31;
        float2 t = __half22float2(
            *(const __half2*)(vph + hbase + (size_t)j * 1024 + c2 * 2));
        Vs[j][c2 * 2]     = t.x;
        Vs[j][c2 * 2 + 1] = t.y;
    }
    __syncthreads();

    // S_tail = S_total - sum_{j<80} Vs[j]
    float2 S2 = *(const float2*)(gS + (size_t)b * 1024 + h * D_ + lane * 2);
#pragma unroll 4
    for (int j = 0; j < WMAX; j++) {
        S2.x -= Vs[j][lane * 2];
        S2.y -= Vs[j][lane * 2 + 1];
    }

    for (int rq = 0; rq < 4; rq++) {
        const int ibase = chunk * 128 + w * 16 + rq * 4;
        float cr[4];
#pragma unroll
        for (int rr = 0; rr < 4; rr++) {
            const int i = ibase + rr;
            const float2 qv = __half22float2(
                *(const __half2*)(qph + hbase + (size_t)i * 1024 + lane * 2));
            const float2 kv = __half22float2(
                *(const __half2*)(kph + hbase + (size_t)i * 1024 + lane * 2));
            const float p0 = qv.x * kv.x * 0.125f;
            const float p1 = qv.y * kv.y * 0.125f;

            float s = p0 + p1;
#pragma unroll
            for (int off = 1; off < 32; off <<= 1) {
                float t = __shfl_up_sync(0xffffffffu, s, off);
                if (lane >= off) s += t;
            }
            scs[w][rr][2 * lane + 1] = s - p1;
            scs[w][rr][2 * lane + 2] = s;
            if (lane == 0) scs[w][rr][0] = 0.f;
            __syncwarp();

            // unnormalized: e_j = exp(w_j); tail logits contribute 944 * e^0
            float ev[3];
            float zs = 0.f;
#pragma unroll
            for (int t3 = 0; t3 < 3; t3++) {
                int j = lane + 32 * t3;
                if (j < WMAX) {
                    int st = (j > 16) ? (j - 16) : 0;
                    int en = (j + 16 < 64) ? (j + 16) : 64;
                    float e = __expf(scs[w][rr][en] - scs[w][rr][st]);
                    ev[t3] = e;
                    zs += e;
                }
            }
#pragma unroll
            for (int off = 16; off >= 1; off >>= 1)
                zs += __shfl_xor_sync(0xffffffffu, zs, off);

            const float invZ = 1.0f / (zs + 944.0f);
#pragma unroll
            for (int t3 = 0; t3 < 3; t3++) {
                int j = lane + 32 * t3;
                if (j < WMAX) wbuf[w][rr][j] = ev[t3] * invZ;
            }
            cr[rr] = invZ;
            __syncwarp();
        }

        float2 acc[4];
#pragma unroll
        for (int rr = 0; rr < 4; rr++)
            acc[rr] = make_float2(cr[rr] * S2.x, cr[rr] * S2.y);

#pragma unroll 1
        for (int j4 = 0; j4 < WMAX / 4; j4++) {
            const int j = j4 * 4;
            const float2 vv0 = *(const float2*)&Vs[j + 0][lane * 2];
            const float2 vv1 = *(const float2*)&Vs[j + 1][lane * 2];
            const float2 vv2 = *(const float2*)&Vs[j + 2][lane * 2];
            const float2 vv3 = *(const float2*)&Vs[j + 3][lane * 2];
#pragma unroll
            for (int rr = 0; rr < 4; rr++) {
                const float4 aw = *(const float4*)&wbuf[w][rr][j];
                acc[rr].x = fmaf(aw.x, vv0.x, acc[rr].x);
                acc[rr].y = fmaf(aw.x, vv0.y, acc[rr].y);
                acc[rr].x = fmaf(aw.y, vv1.x, acc[rr].x);
                acc[rr].y = fmaf(aw.y, vv1.y, acc[rr].y);
                acc[rr].x = fmaf(aw.z, vv2.x, acc[rr].x);
                acc[rr].y = fmaf(aw.z, vv2.y, acc[rr].y);
                acc[rr].x = fmaf(aw.w, vv3.x, acc[rr].x);
                acc[rr].y = fmaf(aw.w, vv3.y, acc[rr].y);
            }
        }

#pragma unroll
        for (int rr = 0; rr < 4; rr++) {
            const __half h0 = __float2half_rn(acc[rr].x);
            const __half h1 = __float2half_rn(acc[rr].y);
            const size_t rb = (size_t)(b * T_ + ibase + rr) * 1024 + h * D_ + lane * 2;
            *(__half2*)(o1 + rb) = __halves2half2(h0, h1);
        }
        __syncwarp();
    }
}

// ---------------------------------------------------------------------------
extern "C" void kernel_launch(void* const* d_in, const int* in_sizes, int n_in,
                              void* d_out, int out_size)
{
    const float* q  = (const float*)d_in[0];
    const float* k  = (const float*)d_in[1];
    const float* v  = (const float*)d_in[2];
    const float* Wq = (const float*)d_in[3];
    const float* Wk = (const float*)d_in[4];
    const float* Wv = (const float*)d_in[5];
    const float* Wp = (const float*)d_in[6];
    const float* bp = (const float*)d_in[7];
    float* out = (float*)d_out;

    float *gS;
    __half *qph, *kph, *vph, *aq, *ak, *av, *ap, *wq, *wk, *wv, *wp;
    cudaGetSymbolAddress((void**)&gS, g_S);
    cudaGetSymbolAddress((void**)&qph, g_qph);
    cudaGetSymbolAddress((void**)&kph, g_kph);
    cudaGetSymbolAddress((void**)&vph, g_vph);
    cudaGetSymbolAddress((void**)&aq, g_aq);
    cudaGetSymbolAddress((void**)&ak, g_ak);
    cudaGetSymbolAddress((void**)&av, g_av);
    cudaGetSymbolAddress((void**)&ap, g_ap);
    cudaGetSymbolAddress((void**)&wq, g_wq);
    cudaGetSymbolAddress((void**)&wk, g_wk);
    cudaGetSymbolAddress((void**)&wv, g_wv);
    cudaGetSymbolAddress((void**)&wp, g_wp);

    cudaFuncSetAttribute(gemm_f16s, cudaFuncAttributeMaxDynamicSharedMemorySize, GEMM_SMEM);

    const int nA4 = MTOT * C_ / 4;   // 1,048,576
    const int nW4 = C_ * C_ / 4;     // 262,144

    // All 7 splits (all 1-term fp16) in one launch; also zeroes g_S
    SplitJobs J;
    J.src[0] = q;  J.dst[0] = aq; J.n4[0] = nA4;
    J.src[1] = k;  J.dst[1] = ak; J.n4[1] = nA4;
    J.src[2] = v;  J.dst[2] = av; J.n4[2] = nA4;
    J.src[3] = Wq; J.dst[3] = wq; J.n4[3] = nW4;
    J.src[4] = Wk; J.dst[4] = wk; J.n4[4] = nW4;
    J.src[5] = Wv; J.dst[5] = wv; J.n4[5] = nW4;
    J.src[6] = Wp; J.dst[6] = wp; J.n4[6] = nW4;
    J.S = gS;
    split_all_kernel<<<dim3(nA4 / 256, 7), 256>>>(J);

    // Fused Q/K/V projections: all outputs fp16; V job also accumulates
    // per-batch column sums into g_S
    GemmJobs G;
    G.A[0] = av; G.W[0] = wv; G.bias[0] = nullptr; G.Cf[0] = nullptr; G.Ch[0] = vph; G.Ssum[0] = gS;
    G.A[1] = aq; G.W[1] = wq; G.bias[1] = nullptr; G.Cf[1] = nullptr; G.Ch[1] = qph; G.Ssum[1] = nullptr;
    G.A[2] = ak; G.W[2] = wk; G.bias[2] = nullptr; G.Cf[2] = nullptr; G.Ch[2] = kph; G.Ssum[2] = nullptr;
    gemm_f16s<<<dim3(C_ / 256, MTOT / 128, 3), 256, GEMM_SMEM>>>(G);

    dim3 ga(T_ / 128, H_, B_);           // 512 CTAs
    attn_kernel<<<ga, 256>>>(qph, kph, vph, gS, ap);

    // Output projection (+bias), 1-term, fp32 out
    GemmJobs P;
    P.A[0] = ap; P.W[0] = wp; P.bias[0] = bp; P.Cf[0] = out; P.Ch[0] = nullptr; P.Ssum[0] = nullptr;
    P.A[1] = ap; P.W[1] = wp; P.bias[1] = bp; P.Cf[1] = out; P.Ch[1] = nullptr; P.Ssum[1] = nullptr;
    P.A[2] = ap; P.W[2] = wp; P.bias[2] = bp; P.Cf[2] = out; P.Ch[2] = nullptr; P.Ssum[2] = nullptr;
    gemm_f16s<<<dim3(C_ / 256, MTOT / 128, 1), 256, GEMM_SMEM>>>(P);
}